// round 15
// baseline (speedup 1.0000x reference)
#include <cuda_runtime.h>
#include <cuda_fp16.h>
#include <cstdint>

// Problem constants
#define B_ 4
#define T_ 2048
#define C_ 2048
#define H_ 16
#define D_ 128

// Scratch (device globals: allocation-free per harness rules)
__device__ __half g_Qh[(size_t)B_ * H_ * T_ * D_];   // [B,H,T,Dh]
__device__ __half g_Kh[(size_t)B_ * H_ * T_ * D_];
__device__ __half g_Vh[(size_t)B_ * H_ * T_ * D_];
__device__ __half g_ATTh[(size_t)B_ * T_ * C_];      // [B,T,C]
__device__ __half g_xh[(size_t)B_ * T_ * C_];        // half x
__device__ __half g_wqkvh[(size_t)3 * C_ * C_];      // half qkv_w
__device__ __half g_wprojh[(size_t)C_ * C_];         // half proj_w

// ---------------------------------------------------------------------------
// Helpers (sm_80-class PTX only — safe on base sm_103 target)
// ---------------------------------------------------------------------------
__device__ __forceinline__ uint32_t smem_u32(const void* p) {
    uint32_t a;
    asm("{ .reg .u64 t; cvta.to.shared.u64 t, %1; cvt.u32.u64 %0, t; }"
        : "=r"(a) : "l"(p));
    return a;
}
__device__ __forceinline__ void cpa16(uint32_t dst, const void* src) {
    asm volatile("cp.async.cg.shared.global [%0], [%1], 16;"
                 :: "r"(dst), "l"(src));
}
#define CP_COMMIT() asm volatile("cp.async.commit_group;" ::: "memory")
#define CP_WAIT(n)  asm volatile("cp.async.wait_group " #n ";" ::: "memory")

#define LDSM_X4(r0, r1, r2, r3, addr) \
    asm volatile("ldmatrix.sync.aligned.m8n8.x4.shared.b16 {%0,%1,%2,%3}, [%4];" \
        : "=r"(r0), "=r"(r1), "=r"(r2), "=r"(r3) : "r"(addr))
#define LDSM_X4T(r0, r1, r2, r3, addr) \
    asm volatile("ldmatrix.sync.aligned.m8n8.x4.trans.shared.b16 {%0,%1,%2,%3}, [%4];" \
        : "=r"(r0), "=r"(r1), "=r"(r2), "=r"(r3) : "r"(addr))

// D(16x8,f32) += A(16x16,f16) * B(16x8,f16)
__device__ __forceinline__ void mma_h(float c[4], const uint32_t a[4],
                                      const uint32_t b[2]) {
    asm volatile(
        "mma.sync.aligned.m16n8k16.row.col.f32.f16.f16.f32 "
        "{%0,%1,%2,%3}, {%4,%5,%6,%7}, {%8,%9}, {%0,%1,%2,%3};"
        : "+f"(c[0]), "+f"(c[1]), "+f"(c[2]), "+f"(c[3])
        : "r"(a[0]), "r"(a[1]), "r"(a[2]), "r"(a[3]), "r"(b[0]), "r"(b[1]));
}

// ---------------------------------------------------------------------------
// Prep: fp32 -> fp16 convert, all three matrices in one launch (no smem)
// ---------------------------------------------------------------------------
#define NX4  (B_ * T_ * C_ / 4)
#define NQ4  (3 * C_ * C_ / 4)
#define NP4  (C_ * C_ / 4)

__global__ void prep_all(const float4* __restrict__ x,
                         const float4* __restrict__ wqkv,
                         const float4* __restrict__ wproj)
{
    int i = blockIdx.x * blockDim.x + threadIdx.x;
    const float4* src;
    __half* dst;
    int j;
    if (i < NX4)            { src = x;     dst = g_xh;     j = i; }
    else if (i < NX4 + NQ4) { src = wqkv;  dst = g_wqkvh;  j = i - NX4; }
    else if (i < NX4 + NQ4 + NP4) { src = wproj; dst = g_wprojh; j = i - NX4 - NQ4; }
    else return;
    float4 v = src[j];
    __half2 h0 = __floats2half2_rn(v.x, v.y);
    __half2 h1 = __floats2half2_rn(v.z, v.w);
    uint2 u;
    u.x = *(uint32_t*)&h0;
    u.y = *(uint32_t*)&h1;
    ((uint2*)dst)[j] = u;
}

// ===========================================================================
// fp16 GEMM: C[M,N] = A[M,2048] @ W[N,2048]^T + bias[N]   (fp32 accumulate)
// CTA 128x128, 8 warps (2m x 4n) at 64x32. BK=32 (2 x k16), 2-stage cp.async.
// STATIC shared memory: 2 stages x (A 128x80B + B 128x80B) = 40960 B <= 48KB.
// NO cudaFuncSetAttribute, NO dynamic smem.
// mode 0: A=g_xh, W=g_wqkvh, half scatter into g_Qh/g_Kh/g_Vh.
// mode 1: A=g_ATTh, W=g_wprojh, fp32 row-major into Out.
// ===========================================================================
#define GRB 80                           // bytes per smem row (32 halfs + pad)
#define GTILE_B (128 * GRB)              // 10240 per operand per stage
#define GSTG_B (2 * GTILE_B)             // 20480 per stage (A + B)

__global__ void __launch_bounds__(256)
gemm_h(const float* __restrict__ bias, float* __restrict__ Out, int mode)
{
    __shared__ __align__(16) char gsm[2 * GSTG_B];   // 40960 bytes, static
    const __half* A = mode ? g_ATTh : g_xh;
    const __half* W = mode ? g_wprojh : g_wqkvh;
    const int K = C_;

    uint32_t sbase = smem_u32(gsm);

    int tid  = threadIdx.x;
    int lane = tid & 31;
    int warp = tid >> 5;                 // 0..7
    int g    = lane >> 2;
    int tig  = lane & 3;
    int wm   = warp >> 2;                // 0..1  (64 rows)
    int wn   = warp & 3;                 // 0..3  (32 cols)
    int bm   = blockIdx.y << 7;
    int bn   = blockIdx.x << 7;

    // staging: row0 = tid>>2 (0..63), 16B chunk c4 = tid&3; rows row0 + 64s
    int row0 = tid >> 2;
    int c4   = tid & 3;
    const __half* a_src0 = A + (size_t)(bm + row0) * K + c4 * 8;
    const __half* b_src0 = W + (size_t)(bn + row0) * K + c4 * 8;
    uint32_t stg = (uint32_t)(row0 * GRB + c4 * 16);

#define G_STAGE(st, bufi) do {                                                  \
    uint32_t ad = sbase + (uint32_t)(bufi) * GSTG_B + stg;                      \
    uint32_t bd = ad + GTILE_B;                                                 \
    _Pragma("unroll")                                                           \
    for (int s = 0; s < 2; s++)                                                 \
        cpa16(ad + s * (64 * GRB), a_src0 + (size_t)(st) * 32 + (size_t)s * 64 * K); \
    _Pragma("unroll")                                                           \
    for (int s = 0; s < 2; s++)                                                 \
        cpa16(bd + s * (64 * GRB), b_src0 + (size_t)(st) * 32 + (size_t)s * 64 * K); \
    CP_COMMIT();                                                                \
} while (0)

    float acc[4][4][4];
#pragma unroll
    for (int i = 0; i < 4; i++)
#pragma unroll
        for (int j = 0; j < 4; j++)
#pragma unroll
            for (int r = 0; r < 4; r++) acc[i][j][r] = 0.f;

    // ldmatrix per-lane address components (relative to stage base)
    uint32_t a_lane = (uint32_t)((wm * 64 + (lane & 15)) * GRB + ((lane >> 4) << 4));
    uint32_t b_lane = (uint32_t)(GTILE_B +
                      (wn * 32 + ((lane >> 4) << 3) + (lane & 7)) * GRB +
                      (((lane >> 3) & 1) << 4));

    // prologue: stage 0
    G_STAGE(0, 0);

    const int NKT = 64;                  // 2048 / 32
    for (int kt = 0; kt < NKT; kt++) {
        if (kt + 1 < NKT) {
            G_STAGE(kt + 1, (kt + 1) & 1);
            CP_WAIT(1);                  // stage kt complete
        } else {
            CP_WAIT(0);
        }
        __syncthreads();

        uint32_t Sb = sbase + (uint32_t)(kt & 1) * GSTG_B;
#pragma unroll
        for (int ks = 0; ks < 2; ks++) {
            uint32_t af[4][4], bf[4][2];
#pragma unroll
            for (int ma = 0; ma < 4; ma++)
                LDSM_X4(af[ma][0], af[ma][1], af[ma][2], af[ma][3],
                        Sb + a_lane + ma * (16 * GRB) + ks * 32);
#pragma unroll
            for (int np = 0; np < 2; np++)
                LDSM_X4(bf[2 * np][0], bf[2 * np][1], bf[2 * np + 1][0],
                        bf[2 * np + 1][1],
                        Sb + b_lane + np * (16 * GRB) + ks * 32);
#pragma unroll
            for (int ma = 0; ma < 4; ma++)
#pragma unroll
                for (int na = 0; na < 4; na++)
                    mma_h(acc[ma][na], af[ma], bf[na]);
        }
        __syncthreads();                 // done reading buf before re-stage
    }

    // ---- epilogue ----
    int sel = blockIdx.x >> 4;           // mode 0: 0:q 1:k 2:v (BN=128 slice)
    int hh  = blockIdx.x & 15;
    __half* qkv_dst = (sel == 0) ? g_Qh : ((sel == 1) ? g_Kh : g_Vh);

#pragma unroll
    for (int ma = 0; ma < 4; ma++) {
        int r0 = bm + (wm << 6) + (ma << 4) + g;
#pragma unroll
        for (int na = 0; na < 4; na++) {
            int cb = (wn << 5) + (na << 3) + (tig << 1);
            int nglob = bn + cb;
            float b0 = __ldg(bias + nglob);
            float b1 = __ldg(bias + nglob + 1);
            if (mode == 0) {
                __half2 v0 = __floats2half2_rn(acc[ma][na][0] + b0,
                                               acc[ma][na][1] + b1);
                __half2 v1 = __floats2half2_rn(acc[ma][na][2] + b0,
                                               acc[ma][na][3] + b1);
                int bb0 = r0 >> 11, t0 = r0 & 2047;
                int r1 = r0 + 8;
                int bb1 = r1 >> 11, t1 = r1 & 2047;
                *(__half2*)(qkv_dst + (((size_t)(bb0 * H_ + hh)) * T_ + t0) * D_ + cb) = v0;
                *(__half2*)(qkv_dst + (((size_t)(bb1 * H_ + hh)) * T_ + t1) * D_ + cb) = v1;
            } else {
                float2 v0 = make_float2(acc[ma][na][0] + b0, acc[ma][na][1] + b1);
                float2 v1 = make_float2(acc[ma][na][2] + b0, acc[ma][na][3] + b1);
                *(float2*)(Out + (size_t)r0 * C_ + nglob)       = v0;
                *(float2*)(Out + (size_t)(r0 + 8) * C_ + nglob) = v1;
            }
        }
    }
}

// ===========================================================================
// Flash attention (fp16 mma, fp32 softmax/accum), STATIC smem <= 48KB.
// CTA: 64 queries, 8 warps = 4 q-groups (16q) x 2 stripes.
// Q kept in registers (loaded once via ldmatrix from a temporary staging).
// Per kb (64 keys): S warp = 16q x 32keys (kst stripe); softmax via CTA
// reductions; P in its own 9KB buffer; PV warp = 16q x 64d (dst stripe).
// smem: K 17408 + V 17408 + P 9216 + red 1024 = 45056 bytes.
// ===========================================================================
#define ARB 272                           // K/V row stride bytes (128 halfs+pad)
#define PRB 144                           // P row stride bytes (64 halfs + pad)

__global__ void __launch_bounds__(256)
attn_h()
{
    __shared__ __align__(16) __half sK[64 * 136];   // 17408 B (also Q staging)
    __shared__ __align__(16) __half sV[64 * 136];   // 17408 B
    __shared__ __align__(16) __half sP[64 * 72];    // 9216 B
    __shared__ float redm[2 * 64];
    __shared__ float reds[2 * 64];

    uint32_t k_sm = smem_u32(sK);
    uint32_t v_sm = smem_u32(sV);
    uint32_t p_sm = smem_u32(sP);

    int tid  = threadIdx.x;
    int lane = tid & 31;
    int warp = tid >> 5;
    int g    = lane >> 2;
    int t    = lane & 3;
    int qg   = warp >> 1;                 // 0..3 : q rows [16qg, 16qg+16)
    int kst  = warp & 1;                  // S key stripe (32 keys)
    int dst  = warp & 1;                  // PV d stripe (64 halfs)

    int qb = (int)gridDim.x - 1 - (int)blockIdx.x;   // heavy blocks first
    int bh = blockIdx.y;
    size_t bhoff = (size_t)bh * T_ * D_;

    // staging: 64 rows x 16 chunks of 16B; chunk id = tid + 256*s
    int row0 = tid >> 4;                  // 0..15
    int cc4  = tid & 15;
    uint32_t dst_off = (uint32_t)(row0 * ARB + cc4 * 16);
    size_t   src_off = (size_t)row0 * D_ + cc4 * 8;

    // ---- Q: stage into sK, load fragments to registers, then free sK ----
    {
        const __half* qsrc = g_Qh + bhoff + (size_t)qb * 64 * D_ + src_off;
#pragma unroll
        for (int s = 0; s < 4; s++)
            cpa16(k_sm + dst_off + s * (16 * ARB), qsrc + (size_t)s * 16 * D_);
        CP_COMMIT();
        CP_WAIT(0);
        __syncthreads();
    }
    uint32_t qa_lane = (uint32_t)(((qg << 4) + (lane & 15)) * ARB + ((lane >> 4) << 4));
    uint32_t qf[8][4];
#pragma unroll
    for (int ks = 0; ks < 8; ks++)
        LDSM_X4(qf[ks][0], qf[ks][1], qf[ks][2], qf[ks][3],
                k_sm + qa_lane + ks * 32);
    __syncthreads();                      // all warps done reading Q from sK

    // ldmatrix per-lane address components
    uint32_t kb_rel = (uint32_t)(((kst << 5) + ((lane >> 4) << 3) + (lane & 7)) * ARB +
                                 (((lane >> 3) & 1) << 4));
    uint32_t vb_rel = (uint32_t)(((((lane >> 3) & 1) << 3) + (lane & 7)) * ARB +
                                 (uint32_t)dst * 128 + ((lane >> 4) << 4));
    uint32_t pa_lane = (uint32_t)(((qg << 4) + (lane & 15)) * PRB + ((lane >> 4) << 4));

    float oacc[8][4];
#pragma unroll
    for (int i = 0; i < 8; i++)
#pragma unroll
        for (int r = 0; r < 4; r++) oacc[i][r] = 0.f;
    float m_i[2] = {-1.0e30f, -1.0e30f};
    float l_i[2] = {0.f, 0.f};

    const float scale = 0.088388347648318447f;   // 1/sqrt(128)

    for (int kb = 0; kb <= qb; kb++) {
        bool diag = (kb == qb);

        // stage K and V for this 64-key block (single-buffered)
        {
            const __half* ksrc = g_Kh + bhoff + (size_t)kb * 64 * D_ + src_off;
            const __half* vsrc = g_Vh + bhoff + (size_t)kb * 64 * D_ + src_off;
#pragma unroll
            for (int s = 0; s < 4; s++)
                cpa16(k_sm + dst_off + s * (16 * ARB), ksrc + (size_t)s * 16 * D_);
#pragma unroll
            for (int s = 0; s < 4; s++)
                cpa16(v_sm + dst_off + s * (16 * ARB), vsrc + (size_t)s * 16 * D_);
            CP_COMMIT();
            CP_WAIT(0);
        }
        __syncthreads();

        // ---- S = Q K^T : warp 16q x 32keys, 8 ks of d16 ----
        float sacc[4][4];
#pragma unroll
        for (int j = 0; j < 4; j++)
#pragma unroll
            for (int r = 0; r < 4; r++) sacc[j][r] = 0.f;

#pragma unroll
        for (int ks = 0; ks < 8; ks++) {
            uint32_t kf[4][2];
#pragma unroll
            for (int np = 0; np < 2; np++)
                LDSM_X4(kf[2 * np][0], kf[2 * np][1], kf[2 * np + 1][0],
                        kf[2 * np + 1][1],
                        k_sm + kb_rel + np * (16 * ARB) + ks * 32);
#pragma unroll
            for (int na = 0; na < 4; na++)
                mma_h(sacc[na], qf[ks], kf[na]);
        }

        // ---- softmax (fp32): mask, stripe-local row max -> CTA combine ----
        float rmax[2] = {-1.0e30f, -1.0e30f};
#pragma unroll
        for (int na = 0; na < 4; na++)
#pragma unroll
            for (int h = 0; h < 2; h++)
#pragma unroll
                for (int e = 0; e < 2; e++) {
                    int col_l = (kst << 5) + (na << 3) + (t << 1) + e;
                    int row_l = (qg << 4) + g + (h << 3);
                    float s = sacc[na][(h << 1) + e] * scale;
                    if (diag && col_l > row_l) s = -1.0e30f;
                    sacc[na][(h << 1) + e] = s;
                    rmax[h] = fmaxf(rmax[h], s);
                }
#pragma unroll
        for (int r = 0; r < 2; r++) {
            rmax[r] = fmaxf(rmax[r], __shfl_xor_sync(0xffffffffu, rmax[r], 1));
            rmax[r] = fmaxf(rmax[r], __shfl_xor_sync(0xffffffffu, rmax[r], 2));
        }
        if (t == 0) {
#pragma unroll
            for (int h = 0; h < 2; h++)
                redm[(kst << 6) + (qg << 4) + g + (h << 3)] = rmax[h];
        }
        __syncthreads();

        float mnew[2], alpha[2], rsum[2];
#pragma unroll
        for (int h = 0; h < 2; h++) {
            int row_l = (qg << 4) + g + (h << 3);
            float m2 = fmaxf(redm[row_l], redm[64 + row_l]);
            mnew[h] = fmaxf(m_i[h], m2);
            alpha[h] = __expf(m_i[h] - mnew[h]);
            m_i[h] = mnew[h];
            rsum[h] = 0.f;
        }
        // p = exp(s - m) (fp32), store half into sP
#pragma unroll
        for (int h = 0; h < 2; h++) {
            int row_l = (qg << 4) + g + (h << 3);
            __half* prow = sP + (size_t)row_l * 72 + (kst << 5);
#pragma unroll
            for (int na = 0; na < 4; na++) {
                float p0 = __expf(sacc[na][(h << 1) + 0] - mnew[h]);
                float p1 = __expf(sacc[na][(h << 1) + 1] - mnew[h]);
                rsum[h] += p0 + p1;
                *(__half2*)(prow + (na << 3) + (t << 1)) =
                    __floats2half2_rn(p0, p1);
            }
        }
#pragma unroll
        for (int r = 0; r < 2; r++) {
            rsum[r] += __shfl_xor_sync(0xffffffffu, rsum[r], 1);
            rsum[r] += __shfl_xor_sync(0xffffffffu, rsum[r], 2);
        }
        if (t == 0) {
#pragma unroll
            for (int h = 0; h < 2; h++)
                reds[(kst << 6) + (qg << 4) + g + (h << 3)] = rsum[h];
        }
        __syncthreads();

#pragma unroll
        for (int h = 0; h < 2; h++) {
            int row_l = (qg << 4) + g + (h << 3);
            l_i[h] = l_i[h] * alpha[h] + (reds[row_l] + reds[64 + row_l]);
        }
#pragma unroll
        for (int na = 0; na < 8; na++) {
            oacc[na][0] *= alpha[0];
            oacc[na][1] *= alpha[0];
            oacc[na][2] *= alpha[1];
            oacc[na][3] *= alpha[1];
        }

        // ---- O += P V : warp 16q x 64d over 64 keys (4 kc of key16) ----
#pragma unroll
        for (int kc = 0; kc < 4; kc++) {
            uint32_t pa[4], vf[8][2];
            LDSM_X4(pa[0], pa[1], pa[2], pa[3],
                    p_sm + pa_lane + kc * 32);
#pragma unroll
            for (int nt = 0; nt < 4; nt++)
                LDSM_X4T(vf[2 * nt][0], vf[2 * nt][1], vf[2 * nt + 1][0],
                         vf[2 * nt + 1][1],
                         v_sm + vb_rel + kc * (16 * ARB) + nt * 32);
#pragma unroll
            for (int na = 0; na < 8; na++)
                mma_h(oacc[na], pa, vf[na]);
        }
        __syncthreads();                  // done reading sK/sV/sP this kb
    }

    // ---- epilogue: normalize, half-round, write g_ATTh [B,T,C] ----
    int b  = bh >> 4;
    int hh = bh & 15;
    float inv0 = 1.f / l_i[0];
    float inv1 = 1.f / l_i[1];
    int tg0 = (qb << 6) + (qg << 4) + g;
    size_t base0 = ((size_t)b * T_ + tg0) * C_ + (hh << 7);
    size_t base1 = ((size_t)b * T_ + tg0 + 8) * C_ + (hh << 7);
#pragma unroll
    for (int na = 0; na < 8; na++) {
        int d0 = (dst << 6) + (na << 3) + (t << 1);
        __half2 v0 = __floats2half2_rn(oacc[na][0] * inv0, oacc[na][1] * inv0);
        __half2 v1 = __floats2half2_rn(oacc[na][2] * inv1, oacc[na][3] * inv1);
        *(__half2*)(g_ATTh + base0 + d0) = v0;
        *(__half2*)(g_ATTh + base1 + d0) = v1;
    }
}

// ---------------------------------------------------------------------------
extern "C" void kernel_launch(void* const* d_in, const int* in_sizes, int n_in,
                              void* d_out, int out_size)
{
    const float* x      = (const float*)d_in[0];
    const float* qkv_w  = (const float*)d_in[1];
    const float* qkv_b  = (const float*)d_in[2];
    const float* proj_w = (const float*)d_in[3];
    const float* proj_b = (const float*)d_in[4];
    float* out = (float*)d_out;

    // NOTE: no cudaFuncSetAttribute, no dynamic shared memory anywhere.

    // 0) fp16 conversion of all GEMM inputs (single launch)
    prep_all<<<(NX4 + NQ4 + NP4 + 255) / 256, 256>>>(
        (const float4*)x, (const float4*)qkv_w, (const float4*)proj_w);

    // 1) QKV projection: [8192,2048] @ [6144,2048]^T + b -> g_Qh/g_Kh/g_Vh
    gemm_h<<<dim3(48, 64), 256>>>(qkv_b, nullptr, 0);

    // 2) causal flash attention (fp16 mma, 64q CTAs, static smem) -> g_ATTh
    attn_h<<<dim3(T_ / 64, B_ * H_), 256>>>();

    // 3) output projection: g_ATTh @ proj_w^T + proj_b -> out (fp32)
    gemm_h<<<dim3(16, 64), 256>>>(proj_b, out, 1);
}

// round 16
// speedup vs baseline: 1.2095x; 1.2095x over previous
#include <cuda_runtime.h>
#include <cuda_fp16.h>
#include <cstdint>

// Problem constants
#define B_ 4
#define T_ 2048
#define C_ 2048
#define H_ 16
#define D_ 128

// Scratch (device globals: allocation-free per harness rules)
__device__ __half g_Qh[(size_t)B_ * H_ * T_ * D_];   // [B,H,T,Dh]
__device__ __half g_Kh[(size_t)B_ * H_ * T_ * D_];
__device__ __half g_Vh[(size_t)B_ * H_ * T_ * D_];
__device__ __half g_ATTh[(size_t)B_ * T_ * C_];      // [B,T,C]
__device__ __half g_xh[(size_t)B_ * T_ * C_];        // half x
__device__ __half g_wqkvh[(size_t)3 * C_ * C_];      // half qkv_w
__device__ __half g_wprojh[(size_t)C_ * C_];         // half proj_w

// ---------------------------------------------------------------------------
// Helpers (sm_80-class PTX only — safe on base sm_103 target)
// ---------------------------------------------------------------------------
__device__ __forceinline__ uint32_t smem_u32(const void* p) {
    uint32_t a;
    asm("{ .reg .u64 t; cvta.to.shared.u64 t, %1; cvt.u32.u64 %0, t; }"
        : "=r"(a) : "l"(p));
    return a;
}
__device__ __forceinline__ void cpa16(uint32_t dst, const void* src) {
    asm volatile("cp.async.cg.shared.global [%0], [%1], 16;"
                 :: "r"(dst), "l"(src));
}
#define CP_COMMIT() asm volatile("cp.async.commit_group;" ::: "memory")
#define CP_WAIT(n)  asm volatile("cp.async.wait_group " #n ";" ::: "memory")

#define LDSM_X4(r0, r1, r2, r3, addr) \
    asm volatile("ldmatrix.sync.aligned.m8n8.x4.shared.b16 {%0,%1,%2,%3}, [%4];" \
        : "=r"(r0), "=r"(r1), "=r"(r2), "=r"(r3) : "r"(addr))
#define LDSM_X4T(r0, r1, r2, r3, addr) \
    asm volatile("ldmatrix.sync.aligned.m8n8.x4.trans.shared.b16 {%0,%1,%2,%3}, [%4];" \
        : "=r"(r0), "=r"(r1), "=r"(r2), "=r"(r3) : "r"(addr))

// D(16x8,f32) += A(16x16,f16) * B(16x8,f16)
__device__ __forceinline__ void mma_h(float c[4], const uint32_t a[4],
                                      const uint32_t b[2]) {
    asm volatile(
        "mma.sync.aligned.m16n8k16.row.col.f32.f16.f16.f32 "
        "{%0,%1,%2,%3}, {%4,%5,%6,%7}, {%8,%9}, {%0,%1,%2,%3};"
        : "+f"(c[0]), "+f"(c[1]), "+f"(c[2]), "+f"(c[3])
        : "r"(a[0]), "r"(a[1]), "r"(a[2]), "r"(a[3]), "r"(b[0]), "r"(b[1]));
}

// ---------------------------------------------------------------------------
// Prep: fp32 -> fp16 convert, all three matrices in one launch (no smem)
// ---------------------------------------------------------------------------
#define NX4  (B_ * T_ * C_ / 4)
#define NQ4  (3 * C_ * C_ / 4)
#define NP4  (C_ * C_ / 4)

__global__ void prep_all(const float4* __restrict__ x,
                         const float4* __restrict__ wqkv,
                         const float4* __restrict__ wproj)
{
    int i = blockIdx.x * blockDim.x + threadIdx.x;
    const float4* src;
    __half* dst;
    int j;
    if (i < NX4)            { src = x;     dst = g_xh;     j = i; }
    else if (i < NX4 + NQ4) { src = wqkv;  dst = g_wqkvh;  j = i - NX4; }
    else if (i < NX4 + NQ4 + NP4) { src = wproj; dst = g_wprojh; j = i - NX4 - NQ4; }
    else return;
    float4 v = src[j];
    __half2 h0 = __floats2half2_rn(v.x, v.y);
    __half2 h1 = __floats2half2_rn(v.z, v.w);
    uint2 u;
    u.x = *(uint32_t*)&h0;
    u.y = *(uint32_t*)&h1;
    ((uint2*)dst)[j] = u;
}

// ===========================================================================
// fp16 GEMM — unchanged from Round-15 passing version (static 41KB smem).
// CTA 128x128, 8 warps (2m x 4n) at 64x32. BK=32 (2 x k16), 2-stage cp.async.
// ===========================================================================
#define GRB 80                           // bytes per smem row (32 halfs + pad)
#define GTILE_B (128 * GRB)              // 10240 per operand per stage
#define GSTG_B (2 * GTILE_B)             // 20480 per stage (A + B)

__global__ void __launch_bounds__(256)
gemm_h(const float* __restrict__ bias, float* __restrict__ Out, int mode)
{
    __shared__ __align__(16) char gsm[2 * GSTG_B];   // 40960 bytes, static
    const __half* A = mode ? g_ATTh : g_xh;
    const __half* W = mode ? g_wprojh : g_wqkvh;
    const int K = C_;

    uint32_t sbase = smem_u32(gsm);

    int tid  = threadIdx.x;
    int lane = tid & 31;
    int warp = tid >> 5;                 // 0..7
    int g    = lane >> 2;
    int tig  = lane & 3;
    int wm   = warp >> 2;                // 0..1  (64 rows)
    int wn   = warp & 3;                 // 0..3  (32 cols)
    int bm   = blockIdx.y << 7;
    int bn   = blockIdx.x << 7;

    int row0 = tid >> 2;
    int c4   = tid & 3;
    const __half* a_src0 = A + (size_t)(bm + row0) * K + c4 * 8;
    const __half* b_src0 = W + (size_t)(bn + row0) * K + c4 * 8;
    uint32_t stg = (uint32_t)(row0 * GRB + c4 * 16);

#define G_STAGE(st, bufi) do {                                                  \
    uint32_t ad = sbase + (uint32_t)(bufi) * GSTG_B + stg;                      \
    uint32_t bd = ad + GTILE_B;                                                 \
    _Pragma("unroll")                                                           \
    for (int s = 0; s < 2; s++)                                                 \
        cpa16(ad + s * (64 * GRB), a_src0 + (size_t)(st) * 32 + (size_t)s * 64 * K); \
    _Pragma("unroll")                                                           \
    for (int s = 0; s < 2; s++)                                                 \
        cpa16(bd + s * (64 * GRB), b_src0 + (size_t)(st) * 32 + (size_t)s * 64 * K); \
    CP_COMMIT();                                                                \
} while (0)

    float acc[4][4][4];
#pragma unroll
    for (int i = 0; i < 4; i++)
#pragma unroll
        for (int j = 0; j < 4; j++)
#pragma unroll
            for (int r = 0; r < 4; r++) acc[i][j][r] = 0.f;

    uint32_t a_lane = (uint32_t)((wm * 64 + (lane & 15)) * GRB + ((lane >> 4) << 4));
    uint32_t b_lane = (uint32_t)(GTILE_B +
                      (wn * 32 + ((lane >> 4) << 3) + (lane & 7)) * GRB +
                      (((lane >> 3) & 1) << 4));

    G_STAGE(0, 0);

    const int NKT = 64;                  // 2048 / 32
    for (int kt = 0; kt < NKT; kt++) {
        if (kt + 1 < NKT) {
            G_STAGE(kt + 1, (kt + 1) & 1);
            CP_WAIT(1);
        } else {
            CP_WAIT(0);
        }
        __syncthreads();

        uint32_t Sb = sbase + (uint32_t)(kt & 1) * GSTG_B;
#pragma unroll
        for (int ks = 0; ks < 2; ks++) {
            uint32_t af[4][4], bf[4][2];
#pragma unroll
            for (int ma = 0; ma < 4; ma++)
                LDSM_X4(af[ma][0], af[ma][1], af[ma][2], af[ma][3],
                        Sb + a_lane + ma * (16 * GRB) + ks * 32);
#pragma unroll
            for (int np = 0; np < 2; np++)
                LDSM_X4(bf[2 * np][0], bf[2 * np][1], bf[2 * np + 1][0],
                        bf[2 * np + 1][1],
                        Sb + b_lane + np * (16 * GRB) + ks * 32);
#pragma unroll
            for (int ma = 0; ma < 4; ma++)
#pragma unroll
                for (int na = 0; na < 4; na++)
                    mma_h(acc[ma][na], af[ma], bf[na]);
        }
        __syncthreads();
    }

    int sel = blockIdx.x >> 4;           // mode 0: 0:q 1:k 2:v (BN=128 slice)
    int hh  = blockIdx.x & 15;
    __half* qkv_dst = (sel == 0) ? g_Qh : ((sel == 1) ? g_Kh : g_Vh);

#pragma unroll
    for (int ma = 0; ma < 4; ma++) {
        int r0 = bm + (wm << 6) + (ma << 4) + g;
#pragma unroll
        for (int na = 0; na < 4; na++) {
            int cb = (wn << 5) + (na << 3) + (tig << 1);
            int nglob = bn + cb;
            float b0 = __ldg(bias + nglob);
            float b1 = __ldg(bias + nglob + 1);
            if (mode == 0) {
                __half2 v0 = __floats2half2_rn(acc[ma][na][0] + b0,
                                               acc[ma][na][1] + b1);
                __half2 v1 = __floats2half2_rn(acc[ma][na][2] + b0,
                                               acc[ma][na][3] + b1);
                int bb0 = r0 >> 11, t0 = r0 & 2047;
                int r1 = r0 + 8;
                int bb1 = r1 >> 11, t1 = r1 & 2047;
                *(__half2*)(qkv_dst + (((size_t)(bb0 * H_ + hh)) * T_ + t0) * D_ + cb) = v0;
                *(__half2*)(qkv_dst + (((size_t)(bb1 * H_ + hh)) * T_ + t1) * D_ + cb) = v1;
            } else {
                float2 v0 = make_float2(acc[ma][na][0] + b0, acc[ma][na][1] + b1);
                float2 v1 = make_float2(acc[ma][na][2] + b0, acc[ma][na][3] + b1);
                *(float2*)(Out + (size_t)r0 * C_ + nglob)       = v0;
                *(float2*)(Out + (size_t)(r0 + 8) * C_ + nglob) = v1;
            }
        }
    }
}

// ===========================================================================
// Flash attention (fp16 mma, fp32 softmax/accum), STATIC smem <= 48KB.
// Round-15 structure with SOFTWARE-PIPELINED staging on the same buffers:
//   - V(kb) issued at loop top (after sV is free), awaited just before PV
//   - K(kb+1) issued right after the post-S barrier (sK free from there on)
// Commit-group ledger: top outstanding = {K(kb)} -> CP_WAIT(0);
// pre-PV: {V(kb), K(kb+1)?} -> CP_WAIT(1) if kb<qb else CP_WAIT(0).
// ===========================================================================
#define ARB 272                           // K/V row stride bytes (128 halfs+pad)
#define PRB 144                           // P row stride bytes (64 halfs + pad)

__global__ void __launch_bounds__(256)
attn_h()
{
    __shared__ __align__(16) __half sK[64 * 136];   // 17408 B (also Q staging)
    __shared__ __align__(16) __half sV[64 * 136];   // 17408 B
    __shared__ __align__(16) __half sP[64 * 72];    // 9216 B
    __shared__ float redm[2 * 64];
    __shared__ float reds[2 * 64];

    uint32_t k_sm = smem_u32(sK);
    uint32_t v_sm = smem_u32(sV);
    uint32_t p_sm = smem_u32(sP);

    int tid  = threadIdx.x;
    int lane = tid & 31;
    int warp = tid >> 5;
    int g    = lane >> 2;
    int t    = lane & 3;
    int qg   = warp >> 1;                 // 0..3 : q rows [16qg, 16qg+16)
    int kst  = warp & 1;                  // S key stripe (32 keys)
    int dst  = warp & 1;                  // PV d stripe (64 halfs)

    int qb = (int)gridDim.x - 1 - (int)blockIdx.x;   // heavy blocks first
    int bh = blockIdx.y;
    size_t bhoff = (size_t)bh * T_ * D_;

    // staging: 64 rows x 16 chunks of 16B; chunk id = tid + 256*s
    int row0 = tid >> 4;                  // 0..15
    int cc4  = tid & 15;
    uint32_t dst_off = (uint32_t)(row0 * ARB + cc4 * 16);
    size_t   src_off = (size_t)row0 * D_ + cc4 * 8;

    // ---- Q: stage into sK, load fragments to registers, then free sK ----
    {
        const __half* qsrc = g_Qh + bhoff + (size_t)qb * 64 * D_ + src_off;
#pragma unroll
        for (int s = 0; s < 4; s++)
            cpa16(k_sm + dst_off + s * (16 * ARB), qsrc + (size_t)s * 16 * D_);
        CP_COMMIT();
        CP_WAIT(0);
        __syncthreads();
    }
    uint32_t qa_lane = (uint32_t)(((qg << 4) + (lane & 15)) * ARB + ((lane >> 4) << 4));
    uint32_t qf[8][4];
#pragma unroll
    for (int ks = 0; ks < 8; ks++)
        LDSM_X4(qf[ks][0], qf[ks][1], qf[ks][2], qf[ks][3],
                k_sm + qa_lane + ks * 32);
    __syncthreads();                      // all warps done reading Q from sK

    // Prologue: issue K(0) into sK (group outstanding at loop top)
    {
        const __half* ksrc = g_Kh + bhoff + src_off;
#pragma unroll
        for (int s = 0; s < 4; s++)
            cpa16(k_sm + dst_off + s * (16 * ARB), ksrc + (size_t)s * 16 * D_);
        CP_COMMIT();
    }

    // ldmatrix per-lane address components
    uint32_t kb_rel = (uint32_t)(((kst << 5) + ((lane >> 4) << 3) + (lane & 7)) * ARB +
                                 (((lane >> 3) & 1) << 4));
    uint32_t vb_rel = (uint32_t)(((((lane >> 3) & 1) << 3) + (lane & 7)) * ARB +
                                 (uint32_t)dst * 128 + ((lane >> 4) << 4));
    uint32_t pa_lane = (uint32_t)(((qg << 4) + (lane & 15)) * PRB + ((lane >> 4) << 4));

    float oacc[8][4];
#pragma unroll
    for (int i = 0; i < 8; i++)
#pragma unroll
        for (int r = 0; r < 4; r++) oacc[i][r] = 0.f;
    float m_i[2] = {-1.0e30f, -1.0e30f};
    float l_i[2] = {0.f, 0.f};

    const float scale = 0.088388347648318447f;   // 1/sqrt(128)

    for (int kb = 0; kb <= qb; kb++) {
        bool diag = (kb == qb);

        // K(kb) is the only outstanding group -> wait it, then barrier
        // (barrier also guarantees prior PV finished reading sV/sP).
        CP_WAIT(0);
        __syncthreads();

        // Issue V(kb) now; awaited just before PV (hides under S + softmax).
        {
            const __half* vsrc = g_Vh + bhoff + (size_t)kb * 64 * D_ + src_off;
#pragma unroll
            for (int s = 0; s < 4; s++)
                cpa16(v_sm + dst_off + s * (16 * ARB), vsrc + (size_t)s * 16 * D_);
            CP_COMMIT();
        }

        // ---- S = Q K^T : warp 16q x 32keys, 8 ks of d16 ----
        float sacc[4][4];
#pragma unroll
        for (int j = 0; j < 4; j++)
#pragma unroll
            for (int r = 0; r < 4; r++) sacc[j][r] = 0.f;

#pragma unroll
        for (int ks = 0; ks < 8; ks++) {
            uint32_t kf[4][2];
#pragma unroll
            for (int np = 0; np < 2; np++)
                LDSM_X4(kf[2 * np][0], kf[2 * np][1], kf[2 * np + 1][0],
                        kf[2 * np + 1][1],
                        k_sm + kb_rel + np * (16 * ARB) + ks * 32);
#pragma unroll
            for (int na = 0; na < 4; na++)
                mma_h(sacc[na], qf[ks], kf[na]);
        }

        __syncthreads();                  // all warps done reading sK

        // Issue K(kb+1) into sK (hides under softmax + PV).
        if (kb < qb) {
            const __half* ksrc = g_Kh + bhoff + (size_t)(kb + 1) * 64 * D_ + src_off;
#pragma unroll
            for (int s = 0; s < 4; s++)
                cpa16(k_sm + dst_off + s * (16 * ARB), ksrc + (size_t)s * 16 * D_);
            CP_COMMIT();
        }

        // ---- softmax (fp32): mask, stripe-local row max -> CTA combine ----
        float rmax[2] = {-1.0e30f, -1.0e30f};
#pragma unroll
        for (int na = 0; na < 4; na++)
#pragma unroll
            for (int h = 0; h < 2; h++)
#pragma unroll
                for (int e = 0; e < 2; e++) {
                    int col_l = (kst << 5) + (na << 3) + (t << 1) + e;
                    int row_l = (qg << 4) + g + (h << 3);
                    float s = sacc[na][(h << 1) + e] * scale;
                    if (diag && col_l > row_l) s = -1.0e30f;
                    sacc[na][(h << 1) + e] = s;
                    rmax[h] = fmaxf(rmax[h], s);
                }
#pragma unroll
        for (int r = 0; r < 2; r++) {
            rmax[r] = fmaxf(rmax[r], __shfl_xor_sync(0xffffffffu, rmax[r], 1));
            rmax[r] = fmaxf(rmax[r], __shfl_xor_sync(0xffffffffu, rmax[r], 2));
        }
        if (t == 0) {
#pragma unroll
            for (int h = 0; h < 2; h++)
                redm[(kst << 6) + (qg << 4) + g + (h << 3)] = rmax[h];
        }
        __syncthreads();

        float mnew[2], alpha[2], rsum[2];
#pragma unroll
        for (int h = 0; h < 2; h++) {
            int row_l = (qg << 4) + g + (h << 3);
            float m2 = fmaxf(redm[row_l], redm[64 + row_l]);
            mnew[h] = fmaxf(m_i[h], m2);
            alpha[h] = __expf(m_i[h] - mnew[h]);
            m_i[h] = mnew[h];
            rsum[h] = 0.f;
        }
        // p = exp(s - m) (fp32), store half into sP
#pragma unroll
        for (int h = 0; h < 2; h++) {
            int row_l = (qg << 4) + g + (h << 3);
            __half* prow = sP + (size_t)row_l * 72 + (kst << 5);
#pragma unroll
            for (int na = 0; na < 4; na++) {
                float p0 = __expf(sacc[na][(h << 1) + 0] - mnew[h]);
                float p1 = __expf(sacc[na][(h << 1) + 1] - mnew[h]);
                rsum[h] += p0 + p1;
                *(__half2*)(prow + (na << 3) + (t << 1)) =
                    __floats2half2_rn(p0, p1);
            }
        }
#pragma unroll
        for (int r = 0; r < 2; r++) {
            rsum[r] += __shfl_xor_sync(0xffffffffu, rsum[r], 1);
            rsum[r] += __shfl_xor_sync(0xffffffffu, rsum[r], 2);
        }
        if (t == 0) {
#pragma unroll
            for (int h = 0; h < 2; h++)
                reds[(kst << 6) + (qg << 4) + g + (h << 3)] = rsum[h];
        }

        // Wait V(kb): outstanding = {V, K'} if kb<qb else {V}.
        if (kb < qb) { CP_WAIT(1); } else { CP_WAIT(0); }
        __syncthreads();                  // reds+P ready AND V visible

#pragma unroll
        for (int h = 0; h < 2; h++) {
            int row_l = (qg << 4) + g + (h << 3);
            l_i[h] = l_i[h] * alpha[h] + (reds[row_l] + reds[64 + row_l]);
        }
#pragma unroll
        for (int na = 0; na < 8; na++) {
            oacc[na][0] *= alpha[0];
            oacc[na][1] *= alpha[0];
            oacc[na][2] *= alpha[1];
            oacc[na][3] *= alpha[1];
        }

        // ---- O += P V : warp 16q x 64d over 64 keys (4 kc of key16) ----
#pragma unroll
        for (int kc = 0; kc < 4; kc++) {
            uint32_t pa[4], vf[8][2];
            LDSM_X4(pa[0], pa[1], pa[2], pa[3],
                    p_sm + pa_lane + kc * 32);
#pragma unroll
            for (int nt = 0; nt < 4; nt++)
                LDSM_X4T(vf[2 * nt][0], vf[2 * nt][1], vf[2 * nt + 1][0],
                         vf[2 * nt + 1][1],
                         v_sm + vb_rel + kc * (16 * ARB) + nt * 32);
#pragma unroll
            for (int na = 0; na < 8; na++)
                mma_h(oacc[na], pa, vf[na]);
        }
        // no end barrier: next iteration's top barrier covers sV/sP reuse
    }

    // ---- epilogue: normalize, half-round, write g_ATTh [B,T,C] ----
    int b  = bh >> 4;
    int hh = bh & 15;
    float inv0 = 1.f / l_i[0];
    float inv1 = 1.f / l_i[1];
    int tg0 = (qb << 6) + (qg << 4) + g;
    size_t base0 = ((size_t)b * T_ + tg0) * C_ + (hh << 7);
    size_t base1 = ((size_t)b * T_ + tg0 + 8) * C_ + (hh << 7);
#pragma unroll
    for (int na = 0; na < 8; na++) {
        int d0 = (dst << 6) + (na << 3) + (t << 1);
        __half2 v0 = __floats2half2_rn(oacc[na][0] * inv0, oacc[na][1] * inv0);
        __half2 v1 = __floats2half2_rn(oacc[na][2] * inv1, oacc[na][3] * inv1);
        *(__half2*)(g_ATTh + base0 + d0) = v0;
        *(__half2*)(g_ATTh + base1 + d0) = v1;
    }
}

// ---------------------------------------------------------------------------
extern "C" void kernel_launch(void* const* d_in, const int* in_sizes, int n_in,
                              void* d_out, int out_size)
{
    const float* x      = (const float*)d_in[0];
    const float* qkv_w  = (const float*)d_in[1];
    const float* qkv_b  = (const float*)d_in[2];
    const float* proj_w = (const float*)d_in[3];
    const float* proj_b = (const float*)d_in[4];
    float* out = (float*)d_out;

    // NOTE: no cudaFuncSetAttribute, no dynamic shared memory anywhere.

    // 0) fp16 conversion of all GEMM inputs (single launch)
    prep_all<<<(NX4 + NQ4 + NP4 + 255) / 256, 256>>>(
        (const float4*)x, (const float4*)qkv_w, (const float4*)proj_w);

    // 1) QKV projection: [8192,2048] @ [6144,2048]^T + b -> g_Qh/g_Kh/g_Vh
    gemm_h<<<dim3(48, 64), 256>>>(qkv_b, nullptr, 0);

    // 2) causal flash attention (fp16 mma, pipelined staging) -> g_ATTh
    attn_h<<<dim3(T_ / 64, B_ * H_), 256>>>();

    // 3) output projection: g_ATTh @ proj_w^T + proj_b -> out (fp32)
    gemm_h<<<dim3(16, 64), 256>>>(proj_b, out, 1);
}